// round 16
// baseline (speedup 1.0000x reference)
#include <cuda_runtime.h>
#include <cuda_bf16.h>
#include <math.h>
#include <stdint.h>

// Problem constants
#define VSZ  32000
#define ED   512
#define HD   1024
#define NBATCH 32
#define TT   256
#define NS   255              // time steps (T-1)
#define MR   (NS*NBATCH)      // 8160
#define MPAD 8192             // padded rows for tensor-core emit
#define G3   (3*HD)           // 3072
#define NPART 250             // vocab tiles of 128 (32000/128)

// Persistent recurrence config (R13 champion: 256 threads, FFMA2)
#define NCTA 128              // 1 CTA/SM guaranteed resident (<=148)
#define JPC  8                // hidden units per CTA (1024/128)
#define RS   1026             // padded row stride (floats); RS%4==2 -> float2-only SMEM access!
#define SCRS 25               // scratch stride (floats), odd -> conflict-free
#define NGRP 16               // barrier groups (8 CTAs each)

// -------- device scratch (static __device__ arrays: allocation-free) --------
__device__ float g_GI[MR * G3];                 // input-gate preactivations
__device__ float g_Hall[MR * HD];               // all hidden states (fp32)
__device__ float g_TGT[MR];                     // target logits (fp32)
__device__ float g_SUMEXP[MR];                  // sum_v exp(logit)
__device__ float g_PART[(size_t)MR * NPART];    // per-vocab-tile exp partials
__device__ __nv_bfloat16 g_Hbf[(size_t)MPAD * HD];   // Hall in bf16 (padded)
__device__ __nv_bfloat16 g_Wbf[(size_t)VSZ * HD];    // emit_w in bf16
__device__ __nv_bfloat16 g_Ehi[(size_t)VSZ * ED];    // embed_w hi (bf16)
__device__ __nv_bfloat16 g_Elo[(size_t)VSZ * ED];    // embed_w lo (bf16)
__device__ __nv_bfloat16 g_WIhi[(size_t)G3 * ED];    // w_ih hi
__device__ __nv_bfloat16 g_WIlo[(size_t)G3 * ED];    // w_ih lo
__device__ unsigned g_bcnt_grp[NGRP * 32];      // per-group arrival ctrs (128B apart)
__device__ unsigned g_bcnt_root;                // root arrival counter
__device__ volatile unsigned g_bsense;          // barrier sense flag

__device__ __forceinline__ float sigmoidf_(float x) {
    return 1.0f / (1.0f + expf(-x));
}

// ====================== PTX helpers ======================
__device__ __forceinline__ uint32_t smem_u32(const void* p) {
    uint32_t a;
    asm("{ .reg .u64 t; cvta.to.shared.u64 t, %1; cvt.u32.u64 %0, t; }" : "=r"(a) : "l"(p));
    return a;
}
__device__ __forceinline__ void cp_async16(uint32_t s, const void* g) {
    asm volatile("cp.async.cg.shared.global [%0], [%1], 16;" :: "r"(s), "l"(g) : "memory");
}
#define CP_COMMIT()  asm volatile("cp.async.commit_group;" ::: "memory")
#define CP_WAIT0()   asm volatile("cp.async.wait_group 0;" ::: "memory")
#define CP_WAIT1()   asm volatile("cp.async.wait_group 1;" ::: "memory")

__device__ __forceinline__ void ldsm_x4(uint32_t& r0, uint32_t& r1, uint32_t& r2, uint32_t& r3,
                                        uint32_t addr) {
    asm volatile("ldmatrix.sync.aligned.m8n8.x4.shared.b16 {%0,%1,%2,%3}, [%4];"
                 : "=r"(r0), "=r"(r1), "=r"(r2), "=r"(r3) : "r"(addr));
}
__device__ __forceinline__ void mma_bf16(float* c, uint32_t a0, uint32_t a1, uint32_t a2,
                                         uint32_t a3, uint32_t b0, uint32_t b1) {
    asm volatile(
        "mma.sync.aligned.m16n8k16.row.col.f32.bf16.bf16.f32 "
        "{%0,%1,%2,%3}, {%4,%5,%6,%7}, {%8,%9}, {%0,%1,%2,%3};"
        : "+f"(c[0]), "+f"(c[1]), "+f"(c[2]), "+f"(c[3])
        : "r"(a0), "r"(a1), "r"(a2), "r"(a3), "r"(b0), "r"(b1));
}
// packed dual-fp32 FMA: acc.{lo,hi} += a.{lo,hi} * b.{lo,hi}   (SASS FFMA2)
__device__ __forceinline__ void ffma2(unsigned long long& acc,
                                      unsigned long long a, unsigned long long b) {
    asm("fma.rn.f32x2 %0, %1, %2, %0;" : "+l"(acc) : "l"(a), "l"(b));
}

// ============================================================================
// Conversion kernels
// ============================================================================
__global__ void convE_kernel(const float* __restrict__ embed_w)
{
    size_t e0 = ((size_t)blockIdx.x * 256 + threadIdx.x) * 4;
    float4 v = *(const float4*)&embed_w[e0];
    __nv_bfloat16 hx = __float2bfloat16_rn(v.x), hy = __float2bfloat16_rn(v.y);
    __nv_bfloat16 hz = __float2bfloat16_rn(v.z), hw = __float2bfloat16_rn(v.w);
    __nv_bfloat16 lx = __float2bfloat16_rn(v.x - __bfloat162float(hx));
    __nv_bfloat16 ly = __float2bfloat16_rn(v.y - __bfloat162float(hy));
    __nv_bfloat16 lz = __float2bfloat16_rn(v.z - __bfloat162float(hz));
    __nv_bfloat16 lw = __float2bfloat16_rn(v.w - __bfloat162float(hw));
    __nv_bfloat16 hi4[4] = {hx, hy, hz, hw};
    __nv_bfloat16 lo4[4] = {lx, ly, lz, lw};
    *(uint2*)&g_Ehi[e0] = *(const uint2*)hi4;
    *(uint2*)&g_Elo[e0] = *(const uint2*)lo4;
}

__global__ void convWih_kernel(const float* __restrict__ w_ih)
{
    size_t e0 = ((size_t)blockIdx.x * 256 + threadIdx.x) * 4;
    float4 v = *(const float4*)&w_ih[e0];
    __nv_bfloat16 hx = __float2bfloat16_rn(v.x), hy = __float2bfloat16_rn(v.y);
    __nv_bfloat16 hz = __float2bfloat16_rn(v.z), hw = __float2bfloat16_rn(v.w);
    __nv_bfloat16 lx = __float2bfloat16_rn(v.x - __bfloat162float(hx));
    __nv_bfloat16 ly = __float2bfloat16_rn(v.y - __bfloat162float(hy));
    __nv_bfloat16 lz = __float2bfloat16_rn(v.z - __bfloat162float(hz));
    __nv_bfloat16 lw = __float2bfloat16_rn(v.w - __bfloat162float(hw));
    __nv_bfloat16 hi4[4] = {hx, hy, hz, hw};
    __nv_bfloat16 lo4[4] = {lx, ly, lz, lw};
    *(uint2*)&g_WIhi[e0] = *(const uint2*)hi4;
    *(uint2*)&g_WIlo[e0] = *(const uint2*)lo4;
}

__global__ void convW_kernel(const float* __restrict__ emit_w)
{
    size_t e0 = ((size_t)blockIdx.x * 256 + threadIdx.x) * 4;
    float4 v = *(const float4*)&emit_w[e0];
    __nv_bfloat162 p0 = __floats2bfloat162_rn(v.x, v.y);
    __nv_bfloat162 p1 = __floats2bfloat162_rn(v.z, v.w);
    uint2 packed;
    packed.x = *(const uint32_t*)&p0;
    packed.y = *(const uint32_t*)&p1;
    *(uint2*)&g_Wbf[e0] = packed;
}

// ============================================================================
// Kernel 1: GI via split-bf16 HMMA (unchanged; measured 238us, tensor=53%).
// ============================================================================
#define GI_AHI   0
#define GI_ALO   16384
#define GI_BHI   32768
#define GI_BLO   49152
#define GI_STAGE 65536
#define GI_BIAS  131072     // 128 floats
#define GI_ROW   131584     // 128 uint64 byte-offsets
#define GI_SMEM  132608

__global__ void __launch_bounds__(256) gi_mma_kernel(const int* __restrict__ words,
                                                     const float* __restrict__ b_ih)
{
    extern __shared__ char smem[];
    const uint32_t sb = smem_u32(smem);
    const int tid = threadIdx.x;
    const int n0 = blockIdx.x * 128;
    const int m0 = blockIdx.y * 128;

    float*    bias_s = (float*)(smem + GI_BIAS);
    uint64_t* rowoff = (uint64_t*)(smem + GI_ROW);

    if (tid < 128) {
        bias_s[tid] = b_ih[n0 + tid];
        int m = m0 + tid;
        int w = 0;
        if (m < MR) {
            int t = m >> 5, n = m & 31;
            w = words[n * TT + t];
        }
        rowoff[tid] = (uint64_t)w * (ED * 2);
    }
    __syncthreads();

    const char* eHi = (const char*)g_Ehi;
    const char* eLo = (const char*)g_Elo;
    const char* wHi = (const char*)g_WIhi + (size_t)n0 * (ED * 2);
    const char* wLo = (const char*)g_WIlo + (size_t)n0 * (ED * 2);

    auto load_chunk = [&](int c, int s) {
        const uint32_t base = sb + s * GI_STAGE;
#pragma unroll
        for (int i = 0; i < 4; i++) {
            int idx = tid + i * 256;
            int r = idx >> 3, g = idx & 7;
            uint32_t so = (uint32_t)(r * 128 + ((g ^ (r & 7)) << 4));
            uint64_t ro = rowoff[r];
            size_t   ko = (size_t)c * 128 + g * 16;
            cp_async16(base + GI_AHI + so, eHi + ro + ko);
            cp_async16(base + GI_ALO + so, eLo + ro + ko);
            cp_async16(base + GI_BHI + so, wHi + (size_t)r * (ED * 2) + ko);
            cp_async16(base + GI_BLO + so, wLo + (size_t)r * (ED * 2) + ko);
        }
        CP_COMMIT();
    };

    const int lane = tid & 31;
    const int w    = tid >> 5;
    const int wm   = w & 3;
    const int wn   = w >> 2;
    const int quad = lane >> 3;
    const int lrow = lane & 7;
    const int qh   = quad >> 1;
    const int qr   = (quad & 1) << 3;

    int rowA[2], rowB[4];
#pragma unroll
    for (int mt = 0; mt < 2; mt++) rowA[mt] = wm * 32 + mt * 16 + qr + lrow;
#pragma unroll
    for (int np = 0; np < 4; np++) rowB[np] = wn * 64 + np * 16 + qr + lrow;

    float acc[2][8][4];
#pragma unroll
    for (int mt = 0; mt < 2; mt++)
#pragma unroll
        for (int nt = 0; nt < 8; nt++)
#pragma unroll
            for (int j = 0; j < 4; j++) acc[mt][nt][j] = 0.0f;

    load_chunk(0, 0);
    for (int c = 0; c < 8; c++) {
        if (c + 1 < 8) { load_chunk(c + 1, (c + 1) & 1); CP_WAIT1(); }
        else           { CP_WAIT0(); }
        __syncthreads();

        const uint32_t base = sb + (c & 1) * GI_STAGE;
#pragma unroll
        for (int ks = 0; ks < 4; ks++) {
            uint32_t ah[2][4], al[2][4], bh[4][4], bl[4][4];
#pragma unroll
            for (int mt = 0; mt < 2; mt++) {
                int r = rowA[mt];
                uint32_t off = (uint32_t)(r * 128 + (((ks * 2 + qh) ^ (r & 7)) << 4));
                ldsm_x4(ah[mt][0], ah[mt][1], ah[mt][2], ah[mt][3], base + GI_AHI + off);
                ldsm_x4(al[mt][0], al[mt][1], al[mt][2], al[mt][3], base + GI_ALO + off);
            }
#pragma unroll
            for (int np = 0; np < 4; np++) {
                int r = rowB[np];
                uint32_t off = (uint32_t)(r * 128 + (((ks * 2 + qh) ^ (r & 7)) << 4));
                ldsm_x4(bh[np][0], bh[np][1], bh[np][2], bh[np][3], base + GI_BHI + off);
                ldsm_x4(bl[np][0], bl[np][1], bl[np][2], bl[np][3], base + GI_BLO + off);
            }
#pragma unroll
            for (int mt = 0; mt < 2; mt++)
#pragma unroll
                for (int np = 0; np < 4; np++)
#pragma unroll
                    for (int h = 0; h < 2; h++) {
                        float* cc = acc[mt][2 * np + h];
                        mma_bf16(cc, ah[mt][0], ah[mt][1], ah[mt][2], ah[mt][3],
                                 bh[np][h], bh[np][2 + h]);
                        mma_bf16(cc, ah[mt][0], ah[mt][1], ah[mt][2], ah[mt][3],
                                 bl[np][h], bl[np][2 + h]);
                        mma_bf16(cc, al[mt][0], al[mt][1], al[mt][2], al[mt][3],
                                 bh[np][h], bh[np][2 + h]);
                    }
        }
        __syncthreads();
    }

    const int g  = lane >> 2;
    const int cj = (lane & 3) * 2;
#pragma unroll
    for (int mt = 0; mt < 2; mt++) {
        int r0 = m0 + wm * 32 + mt * 16 + g;
#pragma unroll
        for (int nt = 0; nt < 8; nt++) {
            int cc = wn * 64 + nt * 8 + cj;
            float b0 = bias_s[cc], b1 = bias_s[cc + 1];
            if (r0 < MR) {
                float2 v0 = make_float2(acc[mt][nt][0] + b0, acc[mt][nt][1] + b1);
                *(float2*)&g_GI[(size_t)r0 * G3 + n0 + cc] = v0;
            }
            if (r0 + 8 < MR) {
                float2 v1 = make_float2(acc[mt][nt][2] + b0, acc[mt][nt][3] + b1);
                *(float2*)&g_GI[(size_t)(r0 + 8) * G3 + n0 + cc] = v1;
            }
        }
    }
}

// ============================================================================
// Barrier-state init (keeps rnn_persist as launch #6)
// ============================================================================
__global__ void binit_kernel()
{
    int i = threadIdx.x;
    if (i < NGRP * 32) g_bcnt_grp[i] = 0;
    if (i == 0) { g_bcnt_root = 0; g_bsense = 0; }
}

// ============================================================================
// Kernel 2: PERSISTENT fused GRU recurrence (R13 config: 256 thr, FFMA2).
//   NEW: two-level barrier arrival (16 groups x 8 CTAs, padded counters) to
//   cut the 128-way same-address atomic serialization (~3.5K cyc) to ~0.7K.
//   NEW: next-step GI prefetch issued BEFORE the barrier (LDG flies in wait).
// ============================================================================
__device__ __forceinline__ void grid_barrier(int tid, int bid, unsigned ns) {
    __syncthreads();
    if (tid == 0) {
        __threadfence();
        unsigned g = (unsigned)bid >> 3;
        if (atomicAdd(&g_bcnt_grp[g * 32], 1) == 7) {
            atomicExch(&g_bcnt_grp[g * 32], 0);
            if (atomicAdd(&g_bcnt_root, 1) == NGRP - 1) {
                atomicExch(&g_bcnt_root, 0);
                __threadfence();
                g_bsense = ns;
            } else {
                while (g_bsense != ns) __nanosleep(32);
            }
        } else {
            while (g_bsense != ns) __nanosleep(32);
        }
        __threadfence();
    }
    __syncthreads();
}

__global__ void __launch_bounds__(256, 1) rnn_persist_kernel(
    const float* __restrict__ hidden0,
    const float* __restrict__ w_hh,
    const float* __restrict__ b_hh)
{
    extern __shared__ float sm[];
    float* w_s = sm;                 // 24 * RS floats
    float* h_s = sm + 24 * RS;       // 32 * RS floats (also reused as scratch)

    const int tid = threadIdx.x;
    const int bid = blockIdx.x;
    const int j0  = bid * JPC;

    // ---- load w_hh slice once (float4 global -> 2x float2 smem; RS%4==2) ----
#pragma unroll
    for (int it = 0; it < 24; it++) {
        int idx = tid + it * 256;
        int r = idx >> 8;
        int q = idx & 255;
        int grow = (r >> 3) * HD + j0 + (r & 7);
        float4 v = *(const float4*)&w_hh[(size_t)grow * HD + q * 4];
        float* d = &w_s[r * RS + q * 4];
        *(float2*)&d[0] = make_float2(v.x, v.y);
        *(float2*)&d[2] = make_float2(v.z, v.w);
    }

    const int jjblk = tid & 3;
    const int nblk  = (tid >> 2) & 7;
    const int ks    = tid >> 5;
    const int kbase = ks * 128;

    const int n_o  = tid >> 3;
    const int jj_o = tid & 7;
    const int s_jj = jj_o >> 1, s_u = jj_o & 1, s_nb = n_o >> 2, s_i = n_o & 3;
    const float bh_r = b_hh[j0 + jj_o];
    const float bh_z = b_hh[HD + j0 + jj_o];
    const float bh_n = b_hh[2 * HD + j0 + jj_o];
    const int jo = j0 + jj_o;

    unsigned sense = 0;

    // ---- prefetch GI for step 0 ----
    float gi_r, gi_z, gi_n;
    {
        const float* gi = &g_GI[(size_t)n_o * G3];
        gi_r = gi[jo];
        gi_z = gi[HD + jo];
        gi_n = gi[2 * HD + jo];
    }

    for (int t = 0; t < NS; t++) {
        // ---- stage h_{t-1} into SMEM ----
        const float* hsrc = (t == 0) ? hidden0 : &g_Hall[(size_t)(t - 1) * NBATCH * HD];
#pragma unroll
        for (int it = 0; it < 32; it++) {
            int idx = tid + it * 256;
            int n = idx >> 8;
            int q = idx & 255;
            float4 v = *(const float4*)&hsrc[n * HD + q * 4];
            float* d = &h_s[n * RS + q * 4];
            *(float2*)&d[0] = make_float2(v.x, v.y);
            *(float2*)&d[2] = make_float2(v.z, v.w);
        }
        __syncthreads();

        // ---- packed-FMA register tile: 3 gates x 2 jj x 4 n over K/8 ----
        unsigned long long acc[3][2][4];
#pragma unroll
        for (int g = 0; g < 3; g++)
#pragma unroll
            for (int u = 0; u < 2; u++)
#pragma unroll
                for (int i = 0; i < 4; i++) acc[g][u][i] = 0ULL;

        {
            const float* hb = &h_s[nblk * 4 * RS + kbase];
            const float* wb = &w_s[jjblk * 2 * RS + kbase];
#pragma unroll 4
            for (int q = 0; q < 64; q++) {
                int ko = q * 2;
                unsigned long long hv[4];
#pragma unroll
                for (int i = 0; i < 4; i++)
                    hv[i] = *(const unsigned long long*)&hb[i * RS + ko];
#pragma unroll
                for (int g = 0; g < 3; g++) {
#pragma unroll
                    for (int u = 0; u < 2; u++) {
                        unsigned long long wv =
                            *(const unsigned long long*)&wb[(g * 8 + u) * RS + ko];
#pragma unroll
                        for (int i = 0; i < 4; i++)
                            ffma2(acc[g][u][i], wv, hv[i]);
                    }
                }
            }
        }

        float hp = h_s[n_o * RS + jo];
        __syncthreads();

        // ---- split-K reduction via SMEM scratch (sum packed lanes here) ----
        float* scr = h_s;
#pragma unroll
        for (int g = 0; g < 3; g++)
#pragma unroll
            for (int u = 0; u < 2; u++)
#pragma unroll
                for (int i = 0; i < 4; i++) {
                    unsigned long long a = acc[g][u][i];
                    float lo = __uint_as_float((uint32_t)a);
                    float hi = __uint_as_float((uint32_t)(a >> 32));
                    scr[tid * SCRS + g * 8 + u * 4 + i] = lo + hi;
                }
        __syncthreads();

        float gr = bh_r, gz = bh_z, gn = bh_n;
#pragma unroll
        for (int kk = 0; kk < 8; kk++) {
            int st = s_jj | (s_nb << 2) | (kk << 5);
            gr += scr[st * SCRS + 0 * 8 + s_u * 4 + s_i];
            gz += scr[st * SCRS + 1 * 8 + s_u * 4 + s_i];
            gn += scr[st * SCRS + 2 * 8 + s_u * 4 + s_i];
        }

        // ---- fused gate math + h_t writeback ----
        int m = t * NBATCH + n_o;
        float r  = sigmoidf_(gi_r + gr);
        float z  = sigmoidf_(gi_z + gz);
        float nn = tanhf(gi_n + r * gn);
        float h  = (1.0f - z) * nn + z * hp;
        g_Hall[(size_t)m * HD + jo] = h;
        g_Hbf[(size_t)m * HD + jo]  = __float2bfloat16(h);

        // ---- prefetch next-step GI BEFORE barrier (overlaps with wait) ----
        float ngr = 0.f, ngz = 0.f, ngn = 0.f;
        if (t + 1 < NS) {
            const float* gi = &g_GI[(size_t)((t + 1) * NBATCH + n_o) * G3];
            ngr = gi[jo];
            ngz = gi[HD + jo];
            ngn = gi[2 * HD + jo];
        }

        // ---- grid barrier (release h_t to all CTAs) ----
        grid_barrier(tid, bid, sense ^ 1);
        sense ^= 1;

        gi_r = ngr; gi_z = ngz; gi_n = ngn;
    }

    // parity-restoring extra barrier: 256 total -> barrier state returns to 0
    grid_barrier(tid, bid, sense ^ 1);
}

// ============================================================================
// Kernel 4: bf16 HMMA emit GEMM + exp row-sum epilogue (unchanged, proven).
// ============================================================================
#define EM_STAGE 32768
#define EM_BOFF  16384
#define EM_BIAS  65536
#define EM_RED   66048
#define EM_SMEM  67072

__global__ void __launch_bounds__(256) emit_mma_kernel(const float* __restrict__ emit_b)
{
    extern __shared__ char smem[];
    const uint32_t sb = smem_u32(smem);
    const int tid  = threadIdx.x;
    const int bn   = blockIdx.x;
    const int m0   = blockIdx.y * 128;
    const int n0   = bn * 128;

    float* bias_s = (float*)(smem + EM_BIAS);
    float* red    = (float*)(smem + EM_RED);
    if (tid < 128) bias_s[tid] = emit_b[n0 + tid];

    const char* gA = (const char*)g_Hbf + (size_t)m0 * (HD * 2);
    const char* gB = (const char*)g_Wbf + (size_t)n0 * (HD * 2);

    auto load_chunk = [&](int c, int s) {
        const uint32_t aB = sb + s * EM_STAGE;
        const uint32_t bB = aB + EM_BOFF;
#pragma unroll
        for (int i = 0; i < 4; i++) {
            int idx = tid + i * 256;
            int r = idx >> 3, g = idx & 7;
            uint32_t so = (uint32_t)(r * 128 + ((g ^ (r & 7)) << 4));
            cp_async16(aB + so, gA + (size_t)r * 2048 + c * 128 + g * 16);
        }
#pragma unroll
        for (int i = 0; i < 4; i++) {
            int idx = tid + i * 256;
            int r = idx >> 3, g = idx & 7;
            uint32_t so = (uint32_t)(r * 128 + ((g ^ (r & 7)) << 4));
            cp_async16(bB + so, gB + (size_t)r * 2048 + c * 128 + g * 16);
        }
        CP_COMMIT();
    };

    const int lane = tid & 31;
    const int w    = tid >> 5;
    const int wm   = w & 3;
    const int wn   = w >> 2;
    const int quad = lane >> 3;
    const int lrow = lane & 7;
    const int qh   = quad >> 1;
    const int qr   = (quad & 1) << 3;

    int rowA[2], rowB[4];
#pragma unroll
    for (int mt = 0; mt < 2; mt++) rowA[mt] = wm * 32 + mt * 16 + qr + lrow;
#pragma unroll
    for (int np = 0; np < 4; np++) rowB[np] = wn * 64 + np * 16 + qr + lrow;

    float acc[2][8][4];
#pragma unroll
    for (int mt = 0; mt < 2; mt++)
#pragma unroll
        for (int nt = 0; nt < 8; nt++)
#pragma unroll
            for (int j = 0; j < 4; j++) acc[mt][nt][j] = 0.0f;

    load_chunk(0, 0);
    for (int c = 0; c < 16; c++) {
        if (c + 1 < 16) { load_chunk(c + 1, (c + 1) & 1); CP_WAIT1(); }
        else            { CP_WAIT0(); }
        __syncthreads();

        const uint32_t aB = sb + (c & 1) * EM_STAGE;
        const uint32_t bB = aB + EM_BOFF;
#pragma unroll
        for (int ks = 0; ks < 4; ks++) {
            uint32_t a[2][4];
#pragma unroll
            for (int mt = 0; mt < 2; mt++) {
                int r = rowA[mt];
                uint32_t off = (uint32_t)(r * 128 + (((ks * 2 + qh) ^ (r & 7)) << 4));
                ldsm_x4(a[mt][0], a[mt][1], a[mt][2], a[mt][3], aB + off);
            }
            uint32_t b[4][4];
#pragma unroll
            for (int np = 0; np < 4; np++) {
                int r = rowB[np];
                uint32_t off = (uint32_t)(r * 128 + (((ks * 2 + qh) ^ (r & 7)) << 4));
                ldsm_x4(b[np][0], b[np][1], b[np][2], b[np][3], bB + off);
            }
#pragma unroll
            for (int mt = 0; mt < 2; mt++)
#pragma unroll
                for (int np = 0; np < 4; np++)
#pragma unroll
                    for (int h = 0; h < 2; h++)
                        mma_bf16(acc[mt][2 * np + h],
                                 a[mt][0], a[mt][1], a[mt][2], a[mt][3],
                                 b[np][h], b[np][2 + h]);
        }
        __syncthreads();
    }

    const int g   = lane >> 2;
    const int cj  = (lane & 3) * 2;
#pragma unroll
    for (int mt = 0; mt < 2; mt++) {
        float s0 = 0.0f, s1 = 0.0f;
#pragma unroll
        for (int nt = 0; nt < 8; nt++) {
            int col = wn * 64 + nt * 8 + cj;
            float b0 = bias_s[col], b1 = bias_s[col + 1];
            s0 += __expf(acc[mt][nt][0] + b0) + __expf(acc[mt][nt][1] + b1);
            s1 += __expf(acc[mt][nt][2] + b0) + __expf(acc[mt][nt][3] + b1);
        }
        s0 += __shfl_xor_sync(0xffffffffu, s0, 1);
        s0 += __shfl_xor_sync(0xffffffffu, s0, 2);
        s1 += __shfl_xor_sync(0xffffffffu, s1, 1);
        s1 += __shfl_xor_sync(0xffffffffu, s1, 2);
        if ((lane & 3) == 0) {
            red[(wm * 32 + mt * 16 + g    ) * 2 + wn] = s0;
            red[(wm * 32 + mt * 16 + g + 8) * 2 + wn] = s1;
        }
    }
    __syncthreads();
    if (tid < 128) {
        int m = m0 + tid;
        if (m < MR) g_PART[(size_t)m * NPART + bn] = red[tid * 2] + red[tid * 2 + 1];
    }
}

// ============================================================================
// Kernel 5: target logits (fp32, one warp per row)
// ============================================================================
__global__ void tgt_kernel(const int* __restrict__ words,
                           const float* __restrict__ emit_w,
                           const float* __restrict__ emit_b)
{
    int warp = threadIdx.x >> 5, lane = threadIdx.x & 31;
    int m = blockIdx.x * 8 + warp;
    int t = m >> 5, n = m & 31;
    int w = words[n * TT + t + 1];
    const float* h  = &g_Hall[m * HD];
    const float* wr = &emit_w[w * HD];
    float s = 0.0f;
    for (int k = lane; k < HD; k += 32) s += h[k] * wr[k];
#pragma unroll
    for (int o = 16; o; o >>= 1) s += __shfl_down_sync(0xffffffffu, s, o);
    if (lane == 0) g_TGT[m] = s + emit_b[w];
}

// Kernel 6: reduce exp partials (fixed order -> deterministic)
__global__ void lse_kernel()
{
    int warp = threadIdx.x >> 5, lane = threadIdx.x & 31;
    int m = blockIdx.x * 8 + warp;
    float s = 0.0f;
    for (int i = lane; i < NPART; i += 32) s += g_PART[(size_t)m * NPART + i];
#pragma unroll
    for (int o = 16; o; o >>= 1) s += __shfl_down_sync(0xffffffffu, s, o);
    if (lane == 0) g_SUMEXP[m] = s;
}

// Kernel 7: word_marginals
__global__ void marg_kernel(float* __restrict__ out)
{
    __shared__ float red[256];
    int n = blockIdx.x, tid = threadIdx.x;
    float s = 0.0f;
    if (tid < NS) {
        int m = tid * NBATCH + n;
        s = g_TGT[m] - logf(g_SUMEXP[m]);
    }
    red[tid] = s;
    __syncthreads();
    for (int o = 128; o; o >>= 1) {
        if (tid < o) red[tid] += red[tid + o];
        __syncthreads();
    }
    if (tid == 0) out[n] = red[0];
}

// Kernel 8: h_final
__global__ void hfinal_kernel(float* __restrict__ out)
{
    int gid = blockIdx.x * 256 + threadIdx.x;
    out[NBATCH + gid] = g_Hall[(NS - 1) * NBATCH * HD + gid];
}

// ============================================================================
// Launch
// ============================================================================
#define PERSIST_SMEM ((24 * RS + 32 * RS) * 4)   // 229824 bytes

extern "C" void kernel_launch(void* const* d_in, const int* in_sizes, int n_in,
                              void* d_out, int out_size)
{
    (void)in_sizes; (void)n_in; (void)out_size;
    const int*   words   = (const int*)  d_in[0];
    const float* hidden  = (const float*)d_in[1];
    const float* embed_w = (const float*)d_in[2];
    const float* w_ih    = (const float*)d_in[3];
    const float* w_hh    = (const float*)d_in[4];
    const float* b_ih    = (const float*)d_in[5];
    const float* b_hh    = (const float*)d_in[6];
    const float* emit_w  = (const float*)d_in[7];
    const float* emit_b  = (const float*)d_in[8];
    float* out = (float*)d_out;

    cudaFuncSetAttribute(emit_mma_kernel,
                         cudaFuncAttributeMaxDynamicSharedMemorySize, EM_SMEM);
    cudaFuncSetAttribute(gi_mma_kernel,
                         cudaFuncAttributeMaxDynamicSharedMemorySize, GI_SMEM);
    cudaFuncSetAttribute(rnn_persist_kernel,
                         cudaFuncAttributeMaxDynamicSharedMemorySize, PERSIST_SMEM);

    // Phase 0: splits/conversions + input-gate GEMM (split-bf16 HMMA)
    convE_kernel<<<VSZ * ED / (4 * 256), 256>>>(embed_w);       // launch 1
    convWih_kernel<<<G3 * ED / (4 * 256), 256>>>(w_ih);         // launch 2
    convW_kernel<<<VSZ * HD / (4 * 256), 256>>>(emit_w);        // launch 3
    gi_mma_kernel<<<dim3(G3 / 128, MPAD / 128), 256, GI_SMEM>>>(words, b_ih); // launch 4

    // Phase 1: barrier-state init + persistent GRU recurrence
    binit_kernel<<<1, 512>>>();                                 // launch 5
    rnn_persist_kernel<<<NCTA, 256, PERSIST_SMEM>>>(hidden, w_hh, b_hh); // launch 6

    // Phase 2: HMMA emit GEMM + logsumexp + targets
    emit_mma_kernel<<<dim3(NPART, MPAD / 128), 256, EM_SMEM>>>(emit_b);
    tgt_kernel<<<1020, 256>>>(words, emit_w, emit_b);
    lse_kernel<<<1020, 256>>>();

    // Phase 3: outputs
    marg_kernel<<<NBATCH, 256>>>(out);
    hfinal_kernel<<<128, 256>>>(out);
}

// round 17
// speedup vs baseline: 1.0579x; 1.0579x over previous
#include <cuda_runtime.h>
#include <cuda_bf16.h>
#include <math.h>
#include <stdint.h>

// Problem constants
#define VSZ  32000
#define ED   512
#define HD   1024
#define NBATCH 32
#define TT   256
#define NS   255              // time steps (T-1)
#define MR   (NS*NBATCH)      // 8160
#define MPAD 8192             // padded rows for tensor-core emit
#define G3   (3*HD)           // 3072
#define NPART 250             // vocab tiles of 128 (32000/128)

// Persistent recurrence config (R13 champion: 256 threads, FFMA2, 1-ctr barrier)
#define NCTA 128              // 1 CTA/SM guaranteed resident (<=148)
#define JPC  8                // hidden units per CTA (1024/128)
#define RS   1026             // padded row stride (floats); RS%4==2 -> float2-only SMEM access!
#define SCRS 25               // scratch stride (floats), odd -> conflict-free

// -------- device scratch (static __device__ arrays: allocation-free) --------
__device__ float g_GI[MR * G3];                 // input-gate preactivations
__device__ float g_Hall[MR * HD];               // all hidden states (fp32)
__device__ float g_TGT[MR];                     // target logits (fp32)
__device__ float g_SUMEXP[MR];                  // sum_v exp(logit)
__device__ float g_PART[(size_t)MR * NPART];    // per-vocab-tile exp partials
__device__ __nv_bfloat16 g_Hbf[(size_t)MPAD * HD];   // Hall in bf16 (padded)
__device__ __nv_bfloat16 g_Wbf[(size_t)VSZ * HD];    // emit_w in bf16
__device__ __nv_bfloat16 g_Ehi[(size_t)VSZ * ED];    // embed_w hi (bf16)
__device__ __nv_bfloat16 g_Elo[(size_t)VSZ * ED];    // embed_w lo (bf16)
__device__ __nv_bfloat16 g_WIhi[(size_t)G3 * ED];    // w_ih hi
__device__ __nv_bfloat16 g_WIlo[(size_t)G3 * ED];    // w_ih lo
__device__ unsigned g_bcnt;                     // barrier arrival counter
__device__ volatile unsigned g_bsense;          // barrier sense flag

__device__ __forceinline__ float sigmoidf_(float x) {
    return 1.0f / (1.0f + expf(-x));
}

// ====================== PTX helpers ======================
__device__ __forceinline__ uint32_t smem_u32(const void* p) {
    uint32_t a;
    asm("{ .reg .u64 t; cvta.to.shared.u64 t, %1; cvt.u32.u64 %0, t; }" : "=r"(a) : "l"(p));
    return a;
}
__device__ __forceinline__ void cp_async16(uint32_t s, const void* g) {
    asm volatile("cp.async.cg.shared.global [%0], [%1], 16;" :: "r"(s), "l"(g) : "memory");
}
#define CP_COMMIT()  asm volatile("cp.async.commit_group;" ::: "memory")
#define CP_WAIT0()   asm volatile("cp.async.wait_group 0;" ::: "memory")
#define CP_WAIT1()   asm volatile("cp.async.wait_group 1;" ::: "memory")

__device__ __forceinline__ void ldsm_x4(uint32_t& r0, uint32_t& r1, uint32_t& r2, uint32_t& r3,
                                        uint32_t addr) {
    asm volatile("ldmatrix.sync.aligned.m8n8.x4.shared.b16 {%0,%1,%2,%3}, [%4];"
                 : "=r"(r0), "=r"(r1), "=r"(r2), "=r"(r3) : "r"(addr));
}
__device__ __forceinline__ void mma_bf16(float* c, uint32_t a0, uint32_t a1, uint32_t a2,
                                         uint32_t a3, uint32_t b0, uint32_t b1) {
    asm volatile(
        "mma.sync.aligned.m16n8k16.row.col.f32.bf16.bf16.f32 "
        "{%0,%1,%2,%3}, {%4,%5,%6,%7}, {%8,%9}, {%0,%1,%2,%3};"
        : "+f"(c[0]), "+f"(c[1]), "+f"(c[2]), "+f"(c[3])
        : "r"(a0), "r"(a1), "r"(a2), "r"(a3), "r"(b0), "r"(b1));
}
// packed dual-fp32 FMA: acc.{lo,hi} += a.{lo,hi} * b.{lo,hi}   (SASS FFMA2)
__device__ __forceinline__ void ffma2(unsigned long long& acc,
                                      unsigned long long a, unsigned long long b) {
    asm("fma.rn.f32x2 %0, %1, %2, %0;" : "+l"(acc) : "l"(a), "l"(b));
}

// ============================================================================
// Conversion kernels
// ============================================================================
__global__ void convE_kernel(const float* __restrict__ embed_w)
{
    size_t e0 = ((size_t)blockIdx.x * 256 + threadIdx.x) * 4;
    float4 v = *(const float4*)&embed_w[e0];
    __nv_bfloat16 hx = __float2bfloat16_rn(v.x), hy = __float2bfloat16_rn(v.y);
    __nv_bfloat16 hz = __float2bfloat16_rn(v.z), hw = __float2bfloat16_rn(v.w);
    __nv_bfloat16 lx = __float2bfloat16_rn(v.x - __bfloat162float(hx));
    __nv_bfloat16 ly = __float2bfloat16_rn(v.y - __bfloat162float(hy));
    __nv_bfloat16 lz = __float2bfloat16_rn(v.z - __bfloat162float(hz));
    __nv_bfloat16 lw = __float2bfloat16_rn(v.w - __bfloat162float(hw));
    __nv_bfloat16 hi4[4] = {hx, hy, hz, hw};
    __nv_bfloat16 lo4[4] = {lx, ly, lz, lw};
    *(uint2*)&g_Ehi[e0] = *(const uint2*)hi4;
    *(uint2*)&g_Elo[e0] = *(const uint2*)lo4;
}

__global__ void convWih_kernel(const float* __restrict__ w_ih)
{
    size_t e0 = ((size_t)blockIdx.x * 256 + threadIdx.x) * 4;
    float4 v = *(const float4*)&w_ih[e0];
    __nv_bfloat16 hx = __float2bfloat16_rn(v.x), hy = __float2bfloat16_rn(v.y);
    __nv_bfloat16 hz = __float2bfloat16_rn(v.z), hw = __float2bfloat16_rn(v.w);
    __nv_bfloat16 lx = __float2bfloat16_rn(v.x - __bfloat162float(hx));
    __nv_bfloat16 ly = __float2bfloat16_rn(v.y - __bfloat162float(hy));
    __nv_bfloat16 lz = __float2bfloat16_rn(v.z - __bfloat162float(hz));
    __nv_bfloat16 lw = __float2bfloat16_rn(v.w - __bfloat162float(hw));
    __nv_bfloat16 hi4[4] = {hx, hy, hz, hw};
    __nv_bfloat16 lo4[4] = {lx, ly, lz, lw};
    *(uint2*)&g_WIhi[e0] = *(const uint2*)hi4;
    *(uint2*)&g_WIlo[e0] = *(const uint2*)lo4;
}

__global__ void convW_kernel(const float* __restrict__ emit_w)
{
    size_t e0 = ((size_t)blockIdx.x * 256 + threadIdx.x) * 4;
    float4 v = *(const float4*)&emit_w[e0];
    __nv_bfloat162 p0 = __floats2bfloat162_rn(v.x, v.y);
    __nv_bfloat162 p1 = __floats2bfloat162_rn(v.z, v.w);
    uint2 packed;
    packed.x = *(const uint32_t*)&p0;
    packed.y = *(const uint32_t*)&p1;
    *(uint2*)&g_Wbf[e0] = packed;
}

// ============================================================================
// Kernel 1: GI via split-bf16 HMMA (unchanged; measured 238us, tensor=53%).
// ============================================================================
#define GI_AHI   0
#define GI_ALO   16384
#define GI_BHI   32768
#define GI_BLO   49152
#define GI_STAGE 65536
#define GI_BIAS  131072     // 128 floats
#define GI_ROW   131584     // 128 uint64 byte-offsets
#define GI_SMEM  132608

__global__ void __launch_bounds__(256) gi_mma_kernel(const int* __restrict__ words,
                                                     const float* __restrict__ b_ih)
{
    extern __shared__ char smem[];
    const uint32_t sb = smem_u32(smem);
    const int tid = threadIdx.x;
    const int n0 = blockIdx.x * 128;
    const int m0 = blockIdx.y * 128;

    float*    bias_s = (float*)(smem + GI_BIAS);
    uint64_t* rowoff = (uint64_t*)(smem + GI_ROW);

    if (tid < 128) {
        bias_s[tid] = b_ih[n0 + tid];
        int m = m0 + tid;
        int w = 0;
        if (m < MR) {
            int t = m >> 5, n = m & 31;
            w = words[n * TT + t];
        }
        rowoff[tid] = (uint64_t)w * (ED * 2);
    }
    __syncthreads();

    const char* eHi = (const char*)g_Ehi;
    const char* eLo = (const char*)g_Elo;
    const char* wHi = (const char*)g_WIhi + (size_t)n0 * (ED * 2);
    const char* wLo = (const char*)g_WIlo + (size_t)n0 * (ED * 2);

    auto load_chunk = [&](int c, int s) {
        const uint32_t base = sb + s * GI_STAGE;
#pragma unroll
        for (int i = 0; i < 4; i++) {
            int idx = tid + i * 256;
            int r = idx >> 3, g = idx & 7;
            uint32_t so = (uint32_t)(r * 128 + ((g ^ (r & 7)) << 4));
            uint64_t ro = rowoff[r];
            size_t   ko = (size_t)c * 128 + g * 16;
            cp_async16(base + GI_AHI + so, eHi + ro + ko);
            cp_async16(base + GI_ALO + so, eLo + ro + ko);
            cp_async16(base + GI_BHI + so, wHi + (size_t)r * (ED * 2) + ko);
            cp_async16(base + GI_BLO + so, wLo + (size_t)r * (ED * 2) + ko);
        }
        CP_COMMIT();
    };

    const int lane = tid & 31;
    const int w    = tid >> 5;
    const int wm   = w & 3;
    const int wn   = w >> 2;
    const int quad = lane >> 3;
    const int lrow = lane & 7;
    const int qh   = quad >> 1;
    const int qr   = (quad & 1) << 3;

    int rowA[2], rowB[4];
#pragma unroll
    for (int mt = 0; mt < 2; mt++) rowA[mt] = wm * 32 + mt * 16 + qr + lrow;
#pragma unroll
    for (int np = 0; np < 4; np++) rowB[np] = wn * 64 + np * 16 + qr + lrow;

    float acc[2][8][4];
#pragma unroll
    for (int mt = 0; mt < 2; mt++)
#pragma unroll
        for (int nt = 0; nt < 8; nt++)
#pragma unroll
            for (int j = 0; j < 4; j++) acc[mt][nt][j] = 0.0f;

    load_chunk(0, 0);
    for (int c = 0; c < 8; c++) {
        if (c + 1 < 8) { load_chunk(c + 1, (c + 1) & 1); CP_WAIT1(); }
        else           { CP_WAIT0(); }
        __syncthreads();

        const uint32_t base = sb + (c & 1) * GI_STAGE;
#pragma unroll
        for (int ks = 0; ks < 4; ks++) {
            uint32_t ah[2][4], al[2][4], bh[4][4], bl[4][4];
#pragma unroll
            for (int mt = 0; mt < 2; mt++) {
                int r = rowA[mt];
                uint32_t off = (uint32_t)(r * 128 + (((ks * 2 + qh) ^ (r & 7)) << 4));
                ldsm_x4(ah[mt][0], ah[mt][1], ah[mt][2], ah[mt][3], base + GI_AHI + off);
                ldsm_x4(al[mt][0], al[mt][1], al[mt][2], al[mt][3], base + GI_ALO + off);
            }
#pragma unroll
            for (int np = 0; np < 4; np++) {
                int r = rowB[np];
                uint32_t off = (uint32_t)(r * 128 + (((ks * 2 + qh) ^ (r & 7)) << 4));
                ldsm_x4(bh[np][0], bh[np][1], bh[np][2], bh[np][3], base + GI_BHI + off);
                ldsm_x4(bl[np][0], bl[np][1], bl[np][2], bl[np][3], base + GI_BLO + off);
            }
#pragma unroll
            for (int mt = 0; mt < 2; mt++)
#pragma unroll
                for (int np = 0; np < 4; np++)
#pragma unroll
                    for (int h = 0; h < 2; h++) {
                        float* cc = acc[mt][2 * np + h];
                        mma_bf16(cc, ah[mt][0], ah[mt][1], ah[mt][2], ah[mt][3],
                                 bh[np][h], bh[np][2 + h]);
                        mma_bf16(cc, ah[mt][0], ah[mt][1], ah[mt][2], ah[mt][3],
                                 bl[np][h], bl[np][2 + h]);
                        mma_bf16(cc, al[mt][0], al[mt][1], al[mt][2], al[mt][3],
                                 bh[np][h], bh[np][2 + h]);
                    }
        }
        __syncthreads();
    }

    const int g  = lane >> 2;
    const int cj = (lane & 3) * 2;
#pragma unroll
    for (int mt = 0; mt < 2; mt++) {
        int r0 = m0 + wm * 32 + mt * 16 + g;
#pragma unroll
        for (int nt = 0; nt < 8; nt++) {
            int cc = wn * 64 + nt * 8 + cj;
            float b0 = bias_s[cc], b1 = bias_s[cc + 1];
            if (r0 < MR) {
                float2 v0 = make_float2(acc[mt][nt][0] + b0, acc[mt][nt][1] + b1);
                *(float2*)&g_GI[(size_t)r0 * G3 + n0 + cc] = v0;
            }
            if (r0 + 8 < MR) {
                float2 v1 = make_float2(acc[mt][nt][2] + b0, acc[mt][nt][3] + b1);
                *(float2*)&g_GI[(size_t)(r0 + 8) * G3 + n0 + cc] = v1;
            }
        }
    }
}

// ============================================================================
// Barrier-state init
// ============================================================================
__global__ void binit_kernel()
{
    if (threadIdx.x == 0) { g_bcnt = 0; g_bsense = 0; }
}

// ============================================================================
// Kernel 2: PERSISTENT fused GRU recurrence — EXACT R13 champion (3993us).
//   256 threads, FFMA2 inner loop, single-counter sense-reversing barrier,
//   GI prefetch at step top. DO NOT TOUCH (R14/R16 variants both regressed).
// ============================================================================
__device__ __forceinline__ void grid_barrier(int tid, unsigned ns) {
    __syncthreads();
    if (tid == 0) {
        __threadfence();
        if (atomicAdd(&g_bcnt, 1) == NCTA - 1) {
            atomicExch(&g_bcnt, 0);
            __threadfence();
            g_bsense = ns;
        } else {
            while (g_bsense != ns) __nanosleep(32);
        }
        __threadfence();
    }
    __syncthreads();
}

__global__ void __launch_bounds__(256, 1) rnn_persist_kernel(
    const float* __restrict__ hidden0,
    const float* __restrict__ w_hh,
    const float* __restrict__ b_hh)
{
    extern __shared__ float sm[];
    float* w_s = sm;                 // 24 * RS floats
    float* h_s = sm + 24 * RS;       // 32 * RS floats (also reused as scratch)

    const int tid = threadIdx.x;
    const int j0  = blockIdx.x * JPC;

    // ---- load w_hh slice once (float4 global -> 2x float2 smem; RS%4==2) ----
#pragma unroll
    for (int it = 0; it < 24; it++) {
        int idx = tid + it * 256;
        int r = idx >> 8;
        int q = idx & 255;
        int grow = (r >> 3) * HD + j0 + (r & 7);
        float4 v = *(const float4*)&w_hh[(size_t)grow * HD + q * 4];
        float* d = &w_s[r * RS + q * 4];
        *(float2*)&d[0] = make_float2(v.x, v.y);
        *(float2*)&d[2] = make_float2(v.z, v.w);
    }

    const int jjblk = tid & 3;
    const int nblk  = (tid >> 2) & 7;
    const int ks    = tid >> 5;
    const int kbase = ks * 128;

    const int n_o  = tid >> 3;
    const int jj_o = tid & 7;
    const int s_jj = jj_o >> 1, s_u = jj_o & 1, s_nb = n_o >> 2, s_i = n_o & 3;
    const float bh_r = b_hh[j0 + jj_o];
    const float bh_z = b_hh[HD + j0 + jj_o];
    const float bh_n = b_hh[2 * HD + j0 + jj_o];
    const int jo = j0 + jj_o;

    unsigned sense = 0;

    for (int t = 0; t < NS; t++) {
        // ---- prefetch GI operands for this step ----
        const float* gi = &g_GI[(size_t)(t * NBATCH + n_o) * G3];
        float gi_r = gi[jo];
        float gi_z = gi[HD + jo];
        float gi_n = gi[2 * HD + jo];

        // ---- stage h_{t-1} into SMEM ----
        const float* hsrc = (t == 0) ? hidden0 : &g_Hall[(size_t)(t - 1) * NBATCH * HD];
#pragma unroll
        for (int it = 0; it < 32; it++) {
            int idx = tid + it * 256;
            int n = idx >> 8;
            int q = idx & 255;
            float4 v = *(const float4*)&hsrc[n * HD + q * 4];
            float* d = &h_s[n * RS + q * 4];
            *(float2*)&d[0] = make_float2(v.x, v.y);
            *(float2*)&d[2] = make_float2(v.z, v.w);
        }
        __syncthreads();

        // ---- packed-FMA register tile: 3 gates x 2 jj x 4 n over K/8 ----
        unsigned long long acc[3][2][4];
#pragma unroll
        for (int g = 0; g < 3; g++)
#pragma unroll
            for (int u = 0; u < 2; u++)
#pragma unroll
                for (int i = 0; i < 4; i++) acc[g][u][i] = 0ULL;

        {
            const float* hb = &h_s[nblk * 4 * RS + kbase];
            const float* wb = &w_s[jjblk * 2 * RS + kbase];
#pragma unroll 4
            for (int q = 0; q < 64; q++) {
                int ko = q * 2;
                unsigned long long hv[4];
#pragma unroll
                for (int i = 0; i < 4; i++)
                    hv[i] = *(const unsigned long long*)&hb[i * RS + ko];
#pragma unroll
                for (int g = 0; g < 3; g++) {
#pragma unroll
                    for (int u = 0; u < 2; u++) {
                        unsigned long long wv =
                            *(const unsigned long long*)&wb[(g * 8 + u) * RS + ko];
#pragma unroll
                        for (int i = 0; i < 4; i++)
                            ffma2(acc[g][u][i], wv, hv[i]);
                    }
                }
            }
        }

        float hp = h_s[n_o * RS + jo];
        __syncthreads();

        // ---- split-K reduction via SMEM scratch (sum packed lanes here) ----
        float* scr = h_s;
#pragma unroll
        for (int g = 0; g < 3; g++)
#pragma unroll
            for (int u = 0; u < 2; u++)
#pragma unroll
                for (int i = 0; i < 4; i++) {
                    unsigned long long a = acc[g][u][i];
                    float lo = __uint_as_float((uint32_t)a);
                    float hi = __uint_as_float((uint32_t)(a >> 32));
                    scr[tid * SCRS + g * 8 + u * 4 + i] = lo + hi;
                }
        __syncthreads();

        float gr = bh_r, gz = bh_z, gn = bh_n;
#pragma unroll
        for (int kk = 0; kk < 8; kk++) {
            int st = s_jj | (s_nb << 2) | (kk << 5);
            gr += scr[st * SCRS + 0 * 8 + s_u * 4 + s_i];
            gz += scr[st * SCRS + 1 * 8 + s_u * 4 + s_i];
            gn += scr[st * SCRS + 2 * 8 + s_u * 4 + s_i];
        }

        // ---- fused gate math + h_t writeback ----
        int m = t * NBATCH + n_o;
        float r  = sigmoidf_(gi_r + gr);
        float z  = sigmoidf_(gi_z + gz);
        float nn = tanhf(gi_n + r * gn);
        float h  = (1.0f - z) * nn + z * hp;
        g_Hall[(size_t)m * HD + jo] = h;
        g_Hbf[(size_t)m * HD + jo]  = __float2bfloat16(h);

        // ---- grid barrier (release h_t to all CTAs) ----
        grid_barrier(tid, sense ^ 1);
        sense ^= 1;
    }

    // parity-restoring extra barrier: 256 total -> g_bsense/g_bcnt return to 0
    grid_barrier(tid, sense ^ 1);
}

// ============================================================================
// Kernel 4: bf16 HMMA emit GEMM + exp row-sum epilogue.
//   NEW this round: 3-stage cp.async pipeline, ONE __syncthreads per chunk
//   (buffer reuse distance 3 makes the post-MMA barrier provably redundant:
//   loads for chunk c+2 are issued only after chunk c's sync, which implies
//   all threads completed chunk c-1's MMA on the buffer being overwritten).
// ============================================================================
#define EM_STAGE 32768                  // bytes per stage (A 16K + B 16K)
#define EM_BOFF  16384
#define EM_BIAS  98304                  // after 3 stages
#define EM_RED   98816
#define EM_SMEM  99840

__global__ void __launch_bounds__(256) emit_mma_kernel(const float* __restrict__ emit_b)
{
    extern __shared__ char smem[];
    const uint32_t sb = smem_u32(smem);
    const int tid  = threadIdx.x;
    const int bn   = blockIdx.x;
    const int m0   = blockIdx.y * 128;
    const int n0   = bn * 128;

    float* bias_s = (float*)(smem + EM_BIAS);
    float* red    = (float*)(smem + EM_RED);
    if (tid < 128) bias_s[tid] = emit_b[n0 + tid];

    const char* gA = (const char*)g_Hbf + (size_t)m0 * (HD * 2);
    const char* gB = (const char*)g_Wbf + (size_t)n0 * (HD * 2);

    auto load_chunk = [&](int c, int s) {
        const uint32_t aB = sb + s * EM_STAGE;
        const uint32_t bB = aB + EM_BOFF;
#pragma unroll
        for (int i = 0; i < 4; i++) {
            int idx = tid + i * 256;
            int r = idx >> 3, g = idx & 7;
            uint32_t so = (uint32_t)(r * 128 + ((g ^ (r & 7)) << 4));
            cp_async16(aB + so, gA + (size_t)r * 2048 + c * 128 + g * 16);
        }
#pragma unroll
        for (int i = 0; i < 4; i++) {
            int idx = tid + i * 256;
            int r = idx >> 3, g = idx & 7;
            uint32_t so = (uint32_t)(r * 128 + ((g ^ (r & 7)) << 4));
            cp_async16(bB + so, gB + (size_t)r * 2048 + c * 128 + g * 16);
        }
        CP_COMMIT();
    };

    const int lane = tid & 31;
    const int w    = tid >> 5;
    const int wm   = w & 3;
    const int wn   = w >> 2;
    const int quad = lane >> 3;
    const int lrow = lane & 7;
    const int qh   = quad >> 1;
    const int qr   = (quad & 1) << 3;

    int rowA[2], rowB[4];
#pragma unroll
    for (int mt = 0; mt < 2; mt++) rowA[mt] = wm * 32 + mt * 16 + qr + lrow;
#pragma unroll
    for (int np = 0; np < 4; np++) rowB[np] = wn * 64 + np * 16 + qr + lrow;

    float acc[2][8][4];
#pragma unroll
    for (int mt = 0; mt < 2; mt++)
#pragma unroll
        for (int nt = 0; nt < 8; nt++)
#pragma unroll
            for (int j = 0; j < 4; j++) acc[mt][nt][j] = 0.0f;

    // ---- 3-stage pipelined mainloop ----
    load_chunk(0, 0);
    load_chunk(1, 1);
    for (int c = 0; c < 16; c++) {
        if (c + 1 < 16) { CP_WAIT1(); }     // chunk c complete, c+1 may fly
        else            { CP_WAIT0(); }
        __syncthreads();                    // all threads see buffer c; all
                                            // finished MMA on buffer (c-1)%3
        if (c + 2 < 16) load_chunk(c + 2, (c + 2) % 3);

        const uint32_t aB = sb + (c % 3) * EM_STAGE;
        const uint32_t bB = aB + EM_BOFF;
#pragma unroll
        for (int ks = 0; ks < 4; ks++) {
            uint32_t a[2][4];
#pragma unroll
            for (int mt = 0; mt < 2; mt++) {
                int r = rowA[mt];
                uint32_t off = (uint32_t)(r * 128 + (((ks * 2 + qh) ^ (r & 7)) << 4));
                ldsm_x4(a[mt][0], a[mt][1], a[mt][2], a[mt][3], aB + off);
            }
            uint32_t b[4][4];
#pragma unroll
            for (int np = 0; np < 4; np++) {
                int r = rowB[np];
                uint32_t off = (uint32_t)(r * 128 + (((ks * 2 + qh) ^ (r & 7)) << 4));
                ldsm_x4(b[np][0], b[np][1], b[np][2], b[np][3], bB + off);
            }
#pragma unroll
            for (int mt = 0; mt < 2; mt++)
#pragma unroll
                for (int np = 0; np < 4; np++)
#pragma unroll
                    for (int h = 0; h < 2; h++)
                        mma_bf16(acc[mt][2 * np + h],
                                 a[mt][0], a[mt][1], a[mt][2], a[mt][3],
                                 b[np][h], b[np][2 + h]);
        }
    }

    __syncthreads();   // before reusing red[] smem region
    const int g   = lane >> 2;
    const int cj  = (lane & 3) * 2;
#pragma unroll
    for (int mt = 0; mt < 2; mt++) {
        float s0 = 0.0f, s1 = 0.0f;
#pragma unroll
        for (int nt = 0; nt < 8; nt++) {
            int col = wn * 64 + nt * 8 + cj;
            float b0 = bias_s[col], b1 = bias_s[col + 1];
            s0 += __expf(acc[mt][nt][0] + b0) + __expf(acc[mt][nt][1] + b1);
            s1 += __expf(acc[mt][nt][2] + b0) + __expf(acc[mt][nt][3] + b1);
        }
        s0 += __shfl_xor_sync(0xffffffffu, s0, 1);
        s0 += __shfl_xor_sync(0xffffffffu, s0, 2);
        s1 += __shfl_xor_sync(0xffffffffu, s1, 1);
        s1 += __shfl_xor_sync(0xffffffffu, s1, 2);
        if ((lane & 3) == 0) {
            red[(wm * 32 + mt * 16 + g    ) * 2 + wn] = s0;
            red[(wm * 32 + mt * 16 + g + 8) * 2 + wn] = s1;
        }
    }
    __syncthreads();
    if (tid < 128) {
        int m = m0 + tid;
        if (m < MR) g_PART[(size_t)m * NPART + bn] = red[tid * 2] + red[tid * 2 + 1];
    }
}

// ============================================================================
// Kernel 5: target logits (fp32, one warp per row)
// ============================================================================
__global__ void tgt_kernel(const int* __restrict__ words,
                           const float* __restrict__ emit_w,
                           const float* __restrict__ emit_b)
{
    int warp = threadIdx.x >> 5, lane = threadIdx.x & 31;
    int m = blockIdx.x * 8 + warp;
    int t = m >> 5, n = m & 31;
    int w = words[n * TT + t + 1];
    const float* h  = &g_Hall[m * HD];
    const float* wr = &emit_w[w * HD];
    float s = 0.0f;
    for (int k = lane; k < HD; k += 32) s += h[k] * wr[k];
#pragma unroll
    for (int o = 16; o; o >>= 1) s += __shfl_down_sync(0xffffffffu, s, o);
    if (lane == 0) g_TGT[m] = s + emit_b[w];
}

// Kernel 6: reduce exp partials (fixed order -> deterministic)
__global__ void lse_kernel()
{
    int warp = threadIdx.x >> 5, lane = threadIdx.x & 31;
    int m = blockIdx.x * 8 + warp;
    float s = 0.0f;
    for (int i = lane; i < NPART; i += 32) s += g_PART[(size_t)m * NPART + i];
#pragma unroll
    for (int o = 16; o; o >>= 1) s += __shfl_down_sync(0xffffffffu, s, o);
    if (lane == 0) g_SUMEXP[m] = s;
}

// Kernel 7: word_marginals
__global__ void marg_kernel(float* __restrict__ out)
{
    __shared__ float red[256];
    int n = blockIdx.x, tid = threadIdx.x;
    float s = 0.0f;
    if (tid < NS) {
        int m = tid * NBATCH + n;
        s = g_TGT[m] - logf(g_SUMEXP[m]);
    }
    red[tid] = s;
    __syncthreads();
    for (int o = 128; o; o >>= 1) {
        if (tid < o) red[tid] += red[tid + o];
        __syncthreads();
    }
    if (tid == 0) out[n] = red[0];
}

// Kernel 8: h_final
__global__ void hfinal_kernel(float* __restrict__ out)
{
    int gid = blockIdx.x * 256 + threadIdx.x;
    out[NBATCH + gid] = g_Hall[(NS - 1) * NBATCH * HD + gid];
}

// ============================================================================
// Launch
// ============================================================================
#define PERSIST_SMEM ((24 * RS + 32 * RS) * 4)   // 229824 bytes

extern "C" void kernel_launch(void* const* d_in, const int* in_sizes, int n_in,
                              void* d_out, int out_size)
{
    (void)in_sizes; (void)n_in; (void)out_size;
    const int*   words   = (const int*)  d_in[0];
    const float* hidden  = (const float*)d_in[1];
    const float* embed_w = (const float*)d_in[2];
    const float* w_ih    = (const float*)d_in[3];
    const float* w_hh    = (const float*)d_in[4];
    const float* b_ih    = (const float*)d_in[5];
    const float* b_hh    = (const float*)d_in[6];
    const float* emit_w  = (const float*)d_in[7];
    const float* emit_b  = (const float*)d_in[8];
    float* out = (float*)d_out;

    cudaFuncSetAttribute(emit_mma_kernel,
                         cudaFuncAttributeMaxDynamicSharedMemorySize, EM_SMEM);
    cudaFuncSetAttribute(gi_mma_kernel,
                         cudaFuncAttributeMaxDynamicSharedMemorySize, GI_SMEM);
    cudaFuncSetAttribute(rnn_persist_kernel,
                         cudaFuncAttributeMaxDynamicSharedMemorySize, PERSIST_SMEM);

    // Phase 0: splits/conversions + input-gate GEMM (split-bf16 HMMA)
    convE_kernel<<<VSZ * ED / (4 * 256), 256>>>(embed_w);       // launch 1
    convWih_kernel<<<G3 * ED / (4 * 256), 256>>>(w_ih);         // launch 2
    convW_kernel<<<VSZ * HD / (4 * 256), 256>>>(emit_w);        // launch 3
    gi_mma_kernel<<<dim3(G3 / 128, MPAD / 128), 256, GI_SMEM>>>(words, b_ih); // launch 4

    // Phase 1: barrier-state init + persistent GRU recurrence (R13 exact)
    binit_kernel<<<1, 32>>>();                                  // launch 5
    rnn_persist_kernel<<<NCTA, 256, PERSIST_SMEM>>>(hidden, w_hh, b_hh); // launch 6

    // Phase 2: HMMA emit GEMM (3-stage) + logsumexp + targets
    emit_mma_kernel<<<dim3(NPART, MPAD / 128), 256, EM_SMEM>>>(emit_b);
    tgt_kernel<<<1020, 256>>>(words, emit_w, emit_b);
    lse_kernel<<<1020, 256>>>();

    // Phase 3: outputs
    marg_kernel<<<NBATCH, 256>>>(out);
    hfinal_kernel<<<128, 256>>>(out);
}